// round 11
// baseline (speedup 1.0000x reference)
#include <cuda_runtime.h>
#include <cuda_bf16.h>
#include <math.h>
#include <stdint.h>

#define T_TOKENS 32768
#define D_MODEL  1024
#define NCOL     128
#define TOPK     8
#define TILE_M   128
#define KC       64
#define NCHUNK   (D_MODEL / KC)
#define THREADS  256

// ---- smem plan (bytes) ----
#define ST_STRIDE 72
#define ST_BYTES  (128 * ST_STRIDE * 4)     // 36864 per buffer
#define OFF_AT    (2 * ST_BYTES)            // 73728 ; A bf16 tiles, 2 splits
#define SP_BYTES  16384                     // one split tile: [4 ks][128 rows][32B]
#define OFF_WT    (OFF_AT + 2 * SP_BYTES)   // 106496 ; W tiles, 2 buf x 2 splits
#define WT_BUF    (2 * SP_BYTES)
#define SMEM_SZ   (OFF_WT + 2 * WT_BUF)     // 172032
#define CS_STRIDE 132

__device__ __nv_bfloat16 g_Wsp[2][NCHUNK][8192];  // [split][chunk][ks*2048 + e*16 + pos]
__device__ int g_flag_count;
__device__ int g_flag_list[T_TOKENS];

// ---------------- helpers ----------------
__device__ __forceinline__ void cpa16(unsigned int dst, const void* src) {
    asm volatile("cp.async.cg.shared.global [%0], [%1], 16;" :: "r"(dst), "l"(src));
}
__device__ __forceinline__ int kpos(int k) {        // k in [0,16) -> storage slot
    return (k & 1) + 4 * ((k & 7) >> 1) + 2 * (k >> 3);
}
__device__ __forceinline__ uint32_t packbf(__nv_bfloat16 a, __nv_bfloat16 b) {
    return (uint32_t)__bfloat16_as_ushort(a) | ((uint32_t)__bfloat16_as_ushort(b) << 16);
}
__device__ __forceinline__ void mma_bf16(float4& c, uint2 a02, uint2 a13, uint2 b) {
    asm("mma.sync.aligned.m16n8k16.row.col.f32.bf16.bf16.f32 "
        "{%0,%1,%2,%3}, {%4,%5,%6,%7}, {%8,%9}, {%0,%1,%2,%3};"
        : "+f"(c.x), "+f"(c.y), "+f"(c.z), "+f"(c.w)
        : "r"(a02.x), "r"(a13.x), "r"(a02.y), "r"(a13.y), "r"(b.x), "r"(b.y));
}

// ---- shared epilogue (identical math in main & repair paths) ----
__device__ __forceinline__ bool epilogue_token(const float* crow, int gt, int lane,
                                               const float* __restrict__ noise,
                                               const int* __restrict__ mask,
                                               float* __restrict__ out, bool want_idx) {
    float lg0 = crow[lane],      lg1 = crow[lane + 32];
    float rn0 = crow[64 + lane], rn1 = crow[96 + lane];
    float ns0 = 1.f / (1.f + expf(-rn0)) + 0.01f;
    float ns1 = 1.f / (1.f + expf(-rn1)) + 0.01f;
    float v0 = fmaf(noise[gt * 64 + lane],      ns0, lg0);
    float v1 = fmaf(noise[gt * 64 + lane + 32], ns1, lg1);

    float mx = fmaxf(v0, v1);
#pragma unroll
    for (int o = 16; o; o >>= 1) mx = fmaxf(mx, __shfl_xor_sync(0xffffffffu, mx, o));
    float p0 = expf(v0 - mx), p1 = expf(v1 - mx);
    float ssum = p0 + p1;
#pragma unroll
    for (int o = 16; o; o >>= 1) ssum += __shfl_xor_sync(0xffffffffu, ssum, o);
    float inv = 1.f / ssum;
    p0 *= inv; p1 *= inv;
    if (mask[gt * 64 + lane] == 0)      p0 = 0.f;
    if (mask[gt * 64 + lane + 32] == 0) p1 = 0.f;

    float sel_p = 0.f; int sel_i = 0; float topsum = 0.f;
    float prev = 0.f, ptop = 0.f; bool flag = false;
#pragma unroll
    for (int it = 0; it < 9; it++) {     // top-9: last rank only feeds gap flag
        float cp; int ci;
        if (p1 > p0) { cp = p1; ci = lane + 32; } else { cp = p0; ci = lane; }
#pragma unroll
        for (int o = 16; o; o >>= 1) {
            float op = __shfl_xor_sync(0xffffffffu, cp, o);
            int   oi = __shfl_xor_sync(0xffffffffu, ci, o);
            if (op > cp || (op == cp && oi < ci)) { cp = op; ci = oi; }
        }
        if (it == 0) ptop = cp;
        else if (prev - cp < 4e-4f * ptop) flag = true;
        prev = cp;
        if (it < TOPK) {
            topsum += cp;
            if (lane == it) { sel_p = cp; sel_i = ci; }
        }
        if (ci == lane)           p0 = -1.f;
        else if (ci == lane + 32) p1 = -1.f;
    }
    float rinv = 1.f / (topsum + 1e-6f);
    if (lane < TOPK) {
        out[(size_t)gt * TOPK + lane] = sel_p * rinv;
        if (want_idx)
            out[(size_t)T_TOKENS * TOPK + (size_t)gt * TOPK + lane] = (float)sel_i;
    }
    return flag;
}

// ---------------- kernels ----------------
__global__ void zero_kernel() { if (threadIdx.x == 0) g_flag_count = 0; }

__global__ void wsplit_kernel(const float* __restrict__ W) {
    int idx = blockIdx.x * 256 + threadIdx.x;   // 131072 = 1024k x 128e
    int k = idx >> 7, e = idx & 127;
    float x = W[idx];
    __nv_bfloat16 h0 = __float2bfloat16_rn(x);
    float r = x - __bfloat162float(h0);
    __nv_bfloat16 h1 = __float2bfloat16_rn(r);
    int c = k >> 6, ksb = (k >> 4) & 3, kl = k & 15;
    int o = ksb * 2048 + e * 16 + kpos(kl);
    g_Wsp[0][c][o] = h0;
    g_Wsp[1][c][o] = h1;
}

extern __shared__ char smem[];

__global__ void __launch_bounds__(THREADS, 1)
router_mma_kernel(const float* __restrict__ A,
                  const float* __restrict__ noise,
                  const int*   __restrict__ mask,
                  float* __restrict__ out, int out_size)
{
    const int tid = threadIdx.x, warp = tid >> 5, lane = tid & 31;
    const int g = lane >> 2, qc = lane & 3;
    const int t0 = blockIdx.x * TILE_M;
    const int m0 = (warp >> 1) * 32;            // warp token base (local)
    const int n0 = (warp & 1) * 64;             // warp col base
    const uint32_t su = (uint32_t)__cvta_generic_to_shared(smem);

    auto cp_stage = [&](int buf, int c) {       // A fp32: 2048 x 16B
        uint32_t base = su + buf * ST_BYTES;
        const float* asrc = A + (size_t)t0 * D_MODEL + c * KC;
#pragma unroll
        for (int r = 0; r < 8; r++) {
            int q = tid + r * 256, row = q >> 4, ch = q & 15;
            cpa16(base + row * (ST_STRIDE * 4) + ch * 16,
                  asrc + (size_t)row * D_MODEL + ch * 4);
        }
    };
    auto cp_w = [&](int buf, int c) {           // W bf16: 2048 x 16B (pre-permuted)
        uint32_t base = su + OFF_WT + buf * WT_BUF;
#pragma unroll
        for (int r = 0; r < 8; r++) {
            int q = tid + r * 256;
            int sp = q >> 10, o16 = q & 1023;
            cpa16(base + sp * SP_BYTES + o16 * 16, &g_Wsp[sp][c][o16 * 8]);
        }
    };
    auto convert = [&](int buf) {               // fp32 stage -> 2 bf16 split tiles
        const float* st = (const float*)(smem + buf * ST_BYTES);
#pragma unroll
        for (int i = 0; i < 8; i++) {
            int task = warp * 8 + i, rg = task >> 2, blk = task & 3;
            int row = rg * 8 + g;
            const float* sr = st + row * ST_STRIDE + blk * 16;
            float2 xlo = *(const float2*)(sr + 2 * qc);       // k = 2q, 2q+1
            float2 xhi = *(const float2*)(sr + 8 + 2 * qc);   // k = 2q+8, 2q+9
            __nv_bfloat16 l0 = __float2bfloat16_rn(xlo.x), l1 = __float2bfloat16_rn(xlo.y);
            __nv_bfloat16 h0 = __float2bfloat16_rn(xhi.x), h1 = __float2bfloat16_rn(xhi.y);
            uint2 w0 = make_uint2(packbf(l0, l1), packbf(h0, h1));
            uint2 w1 = make_uint2(
                packbf(__float2bfloat16_rn(xlo.x - __bfloat162float(l0)),
                       __float2bfloat16_rn(xlo.y - __bfloat162float(l1))),
                packbf(__float2bfloat16_rn(xhi.x - __bfloat162float(h0)),
                       __float2bfloat16_rn(xhi.y - __bfloat162float(h1))));
            char* dst = smem + OFF_AT + blk * 4096 + row * 32 + qc * 8;
            *(uint2*)(dst)            = w0;
            *(uint2*)(dst + SP_BYTES) = w1;
        }
    };

    float4 acc[2][8];
#pragma unroll
    for (int mt = 0; mt < 2; mt++)
#pragma unroll
        for (int nt = 0; nt < 8; nt++) acc[mt][nt] = make_float4(0.f, 0.f, 0.f, 0.f);

    cp_stage(0, 0); cp_w(0, 0);
    asm volatile("cp.async.commit_group;" ::: "memory");

    for (int c = 0; c < NCHUNK; c++) {
        asm volatile("cp.async.wait_group 0;" ::: "memory");
        __syncthreads();
        if (c + 1 < NCHUNK) {
            cp_stage((c + 1) & 1, c + 1);
            cp_w((c + 1) & 1, c + 1);
            asm volatile("cp.async.commit_group;" ::: "memory");
        }
        convert(c & 1);
        __syncthreads();

        const char* at = smem + OFF_AT;
        const char* wt = smem + OFF_WT + (c & 1) * WT_BUF;
#pragma unroll
        for (int ks = 0; ks < 4; ks++) {
            uint2 a02[2][2], a13[2][2];         // [split][mtile]
#pragma unroll
            for (int sp = 0; sp < 2; sp++)
#pragma unroll
                for (int mt = 0; mt < 2; mt++) {
                    const char* ab = at + sp * SP_BYTES + ks * 4096;
                    int rb = m0 + mt * 16;
                    a02[sp][mt] = *(const uint2*)(ab + (rb + g) * 32 + qc * 8);
                    a13[sp][mt] = *(const uint2*)(ab + (rb + g + 8) * 32 + qc * 8);
                }
#pragma unroll
            for (int nt = 0; nt < 8; nt++) {
                const char* wb = wt + ks * 4096 + (n0 + nt * 8 + g) * 32 + qc * 8;
                uint2 b0 = *(const uint2*)(wb);
                uint2 b1 = *(const uint2*)(wb + SP_BYTES);
#pragma unroll
                for (int mt = 0; mt < 2; mt++) {
                    mma_bf16(acc[mt][nt], a02[0][mt], a13[0][mt], b0);   // a0*w0
                    mma_bf16(acc[mt][nt], a02[0][mt], a13[0][mt], b1);   // a0*w1
                    mma_bf16(acc[mt][nt], a02[1][mt], a13[1][mt], b0);   // a1*w0
                }
            }
        }
        __syncthreads();
    }

    // ---- spill C [128][132] to smem (overwrites dead fp32 stage) ----
    float* Cs = (float*)smem;
#pragma unroll
    for (int mt = 0; mt < 2; mt++)
#pragma unroll
        for (int nt = 0; nt < 8; nt++) {
            int rr = m0 + mt * 16 + g, cc = n0 + nt * 8 + 2 * qc;
            *(float2*)(Cs + rr * CS_STRIDE + cc)       = make_float2(acc[mt][nt].x, acc[mt][nt].y);
            *(float2*)(Cs + (rr + 8) * CS_STRIDE + cc) = make_float2(acc[mt][nt].z, acc[mt][nt].w);
        }
    __syncthreads();

    // ---- epilogue: warp -> tokens warp*16 .. +15 ----
    const bool want_idx = (out_size >= 2 * T_TOKENS * TOPK);
    for (int tt = 0; tt < 16; tt++) {
        int t = warp * 16 + tt, gt = t0 + t;
        bool flag = epilogue_token(Cs + t * CS_STRIDE, gt, lane, noise, mask, out, want_idx);
        if (lane == 0 && flag) {
            int fi = atomicAdd(&g_flag_count, 1);
            if (fi < T_TOKENS) g_flag_list[fi] = gt;
        }
    }
}

__global__ void repair_kernel(const float* __restrict__ A, const float* __restrict__ W,
                              const float* __restrict__ noise, const int* __restrict__ mask,
                              float* __restrict__ out, int out_size)
{
    __shared__ float crow[NCOL];
    int n = g_flag_count; if (n > T_TOKENS) n = T_TOKENS;
    const bool want_idx = (out_size >= 2 * T_TOKENS * TOPK);
    for (int i = blockIdx.x; i < n; i += gridDim.x) {
        int gt = g_flag_list[i];
        const float* arow = A + (size_t)gt * D_MODEL;
        int j = threadIdx.x;
        float acc = 0.f;
        for (int k = 0; k < D_MODEL; k++)       // EXACT fp32 chain, k ascending
            acc = fmaf(arow[k], W[k * NCOL + j], acc);
        crow[j] = acc;
        __syncthreads();
        if (threadIdx.x < 32)
            epilogue_token(crow, gt, threadIdx.x, noise, mask, out, want_idx);
        __syncthreads();
    }
}

extern "C" void kernel_launch(void* const* d_in, const int* in_sizes, int n_in,
                              void* d_out, int out_size)
{
    const float* A     = (const float*)d_in[0];
    const float* W     = (const float*)d_in[1];
    const float* noise = (const float*)d_in[2];
    const int*   mask  = (const int*)d_in[3];
    float* out = (float*)d_out;

    cudaFuncSetAttribute(router_mma_kernel,
                         cudaFuncAttributeMaxDynamicSharedMemorySize, SMEM_SZ);
    zero_kernel<<<1, 32>>>();
    wsplit_kernel<<<512, 256>>>(W);
    router_mma_kernel<<<T_TOKENS / TILE_M, THREADS, SMEM_SZ>>>(A, noise, mask, out, out_size);
    repair_kernel<<<512, NCOL>>>(A, W, noise, mask, out, out_size);
}

// round 14
// speedup vs baseline: 1.7704x; 1.7704x over previous
#include <cuda_runtime.h>
#include <cuda_bf16.h>
#include <math.h>
#include <stdint.h>

#define T_TOKENS 32768
#define D_MODEL  1024
#define NCOL     128
#define TOPK     8
#define TILE_M   128
#define KC       64
#define NCHUNK   (D_MODEL / KC)
#define THREADS  256

// ---- smem plan (bytes) ----
#define ST_STRIDE 72
#define ST_BYTES  (128 * ST_STRIDE * 4)     // 36864 per buffer
#define OFF_AT    (2 * ST_BYTES)            // 73728 ; A bf16 tiles, 2 splits
#define SP_BYTES  16384                     // one split tile: [4 ks][128 rows][32B]
#define OFF_WT    (OFF_AT + 2 * SP_BYTES)   // 106496 ; W tiles, 2 buf x 2 splits
#define WT_BUF    (2 * SP_BYTES)
#define SMEM_SZ   (OFF_WT + 2 * WT_BUF)     // 172032
#define CS_STRIDE 132

#define FLAG_TH   4e-4f                     // R11-proven coverage; do not tighten

__device__ __nv_bfloat16 g_Wsp[2][NCHUNK][8192];  // [split][chunk][ks*2048 + e*16 + pos]
__device__ int g_flag_count;
__device__ int g_flag_list[T_TOKENS];

// ---------------- helpers ----------------
__device__ __forceinline__ void cpa16(unsigned int dst, const void* src) {
    asm volatile("cp.async.cg.shared.global [%0], [%1], 16;" :: "r"(dst), "l"(src));
}
__device__ __forceinline__ int kpos(int k) {        // k in [0,16) -> storage slot
    return (k & 1) + 4 * ((k & 7) >> 1) + 2 * (k >> 3);
}
__device__ __forceinline__ uint32_t cvt2(float xlo, float xhi) {  // lo half = xlo
    uint32_t r;
    asm("cvt.rn.bf16x2.f32 %0, %1, %2;" : "=r"(r) : "f"(xhi), "f"(xlo));
    return r;
}
__device__ __forceinline__ void mma_bf16(float4& c, uint2 a02, uint2 a13, uint2 b) {
    asm("mma.sync.aligned.m16n8k16.row.col.f32.bf16.bf16.f32 "
        "{%0,%1,%2,%3}, {%4,%5,%6,%7}, {%8,%9}, {%0,%1,%2,%3};"
        : "+f"(c.x), "+f"(c.y), "+f"(c.z), "+f"(c.w)
        : "r"(a02.x), "r"(a13.x), "r"(a02.y), "r"(a13.y), "r"(b.x), "r"(b.y));
}

// ---- shared epilogue (identical math in main & repair paths) ----
__device__ __forceinline__ bool epilogue_token(const float* crow, int gt, int lane,
                                               const float* __restrict__ noise,
                                               const int* __restrict__ mask,
                                               float* __restrict__ out, bool want_idx) {
    float lg0 = crow[lane],      lg1 = crow[lane + 32];
    float rn0 = crow[64 + lane], rn1 = crow[96 + lane];
    float ns0 = 1.f / (1.f + expf(-rn0)) + 0.01f;
    float ns1 = 1.f / (1.f + expf(-rn1)) + 0.01f;
    float v0 = fmaf(noise[gt * 64 + lane],      ns0, lg0);
    float v1 = fmaf(noise[gt * 64 + lane + 32], ns1, lg1);

    float mx = fmaxf(v0, v1);
#pragma unroll
    for (int o = 16; o; o >>= 1) mx = fmaxf(mx, __shfl_xor_sync(0xffffffffu, mx, o));
    float p0 = expf(v0 - mx), p1 = expf(v1 - mx);
    float ssum = p0 + p1;
#pragma unroll
    for (int o = 16; o; o >>= 1) ssum += __shfl_xor_sync(0xffffffffu, ssum, o);
    float inv = 1.f / ssum;
    p0 *= inv; p1 *= inv;
    if (mask[gt * 64 + lane] == 0)      p0 = 0.f;
    if (mask[gt * 64 + lane + 32] == 0) p1 = 0.f;

    float sel_p = 0.f; int sel_i = 0; float topsum = 0.f;
    float prev = 0.f, ptop = 0.f; bool flag = false;
#pragma unroll
    for (int it = 0; it < 9; it++) {     // top-9: rank 9 only feeds the gap flag
        float cp; int ci;
        if (p1 > p0) { cp = p1; ci = lane + 32; } else { cp = p0; ci = lane; }
#pragma unroll
        for (int o = 16; o; o >>= 1) {
            float op = __shfl_xor_sync(0xffffffffu, cp, o);
            int   oi = __shfl_xor_sync(0xffffffffu, ci, o);
            if (op > cp || (op == cp && oi < ci)) { cp = op; ci = oi; }
        }
        if (it == 0) ptop = cp;
        else if (prev - cp < FLAG_TH * ptop) flag = true;
        prev = cp;
        if (it < TOPK) {
            topsum += cp;
            if (lane == it) { sel_p = cp; sel_i = ci; }
        }
        if (ci == lane)           p0 = -1.f;
        else if (ci == lane + 32) p1 = -1.f;
    }
    float rinv = 1.f / (topsum + 1e-6f);
    if (lane < TOPK) {
        out[(size_t)gt * TOPK + lane] = sel_p * rinv;
        if (want_idx)
            out[(size_t)T_TOKENS * TOPK + (size_t)gt * TOPK + lane] = (float)sel_i;
    }
    return flag;
}

// ---------------- kernels ----------------
__global__ void zero_kernel() { if (threadIdx.x == 0) g_flag_count = 0; }

__global__ void wsplit_kernel(const float* __restrict__ W) {
    int idx = blockIdx.x * 256 + threadIdx.x;   // 131072 = 1024k x 128e
    int k = idx >> 7, e = idx & 127;
    float x = W[idx];
    __nv_bfloat16 h0 = __float2bfloat16_rn(x);
    float r = x - __bfloat162float(h0);
    __nv_bfloat16 h1 = __float2bfloat16_rn(r);
    int c = k >> 6, ksb = (k >> 4) & 3, kl = k & 15;
    int o = ksb * 2048 + e * 16 + kpos(kl);
    g_Wsp[0][c][o] = h0;
    g_Wsp[1][c][o] = h1;
}

extern __shared__ char smem[];

__global__ void __launch_bounds__(THREADS, 1)
router_mma_kernel(const float* __restrict__ A,
                  const float* __restrict__ noise,
                  const int*   __restrict__ mask,
                  float* __restrict__ out, int out_size)
{
    const int tid = threadIdx.x, warp = tid >> 5, lane = tid & 31;
    const int g = lane >> 2, qc = lane & 3;
    const int t0 = blockIdx.x * TILE_M;
    const int m0 = (warp >> 1) * 32;            // warp token base (local)
    const int n0 = (warp & 1) * 64;             // warp col base
    const uint32_t su = (uint32_t)__cvta_generic_to_shared(smem);

    auto cp_stage = [&](int buf, int c) {       // A fp32: 2048 x 16B
        uint32_t base = su + buf * ST_BYTES;
        const float* asrc = A + (size_t)t0 * D_MODEL + c * KC;
#pragma unroll
        for (int r = 0; r < 8; r++) {
            int q = tid + r * 256, row = q >> 4, ch = q & 15;
            cpa16(base + row * (ST_STRIDE * 4) + ch * 16,
                  asrc + (size_t)row * D_MODEL + ch * 4);
        }
    };
    auto cp_w = [&](int buf, int c) {           // W bf16: 2048 x 16B (pre-permuted)
        uint32_t base = su + OFF_WT + buf * WT_BUF;
#pragma unroll
        for (int r = 0; r < 8; r++) {
            int q = tid + r * 256;
            int sp = q >> 10, o16 = q & 1023;
            cpa16(base + sp * SP_BYTES + o16 * 16, &g_Wsp[sp][c][o16 * 8]);
        }
    };
    auto convert = [&](int buf) {               // fp32 stage -> 2 bf16 split tiles
        const float* st = (const float*)(smem + buf * ST_BYTES);
#pragma unroll
        for (int i = 0; i < 8; i++) {
            int task = warp * 8 + i, rg = task >> 2, blk = task & 3;
            int row = rg * 8 + g;
            const float* sr = st + row * ST_STRIDE + blk * 16;
            float2 xlo = *(const float2*)(sr + 2 * qc);       // k = 2q, 2q+1
            float2 xhi = *(const float2*)(sr + 8 + 2 * qc);   // k = 2q+8, 2q+9
            uint32_t hA = cvt2(xlo.x, xlo.y);
            uint32_t hB = cvt2(xhi.x, xhi.y);
            float rAx = xlo.x - __uint_as_float(hA << 16);
            float rAy = xlo.y - __uint_as_float(hA & 0xFFFF0000u);
            float rBx = xhi.x - __uint_as_float(hB << 16);
            float rBy = xhi.y - __uint_as_float(hB & 0xFFFF0000u);
            uint2 w0 = make_uint2(hA, hB);
            uint2 w1 = make_uint2(cvt2(rAx, rAy), cvt2(rBx, rBy));
            char* dst = smem + OFF_AT + blk * 4096 + row * 32 + qc * 8;
            *(uint2*)(dst)            = w0;
            *(uint2*)(dst + SP_BYTES) = w1;
        }
    };

    float4 acc[2][8];
#pragma unroll
    for (int mt = 0; mt < 2; mt++)
#pragma unroll
        for (int nt = 0; nt < 8; nt++) acc[mt][nt] = make_float4(0.f, 0.f, 0.f, 0.f);

    cp_stage(0, 0); cp_w(0, 0);
    asm volatile("cp.async.commit_group;" ::: "memory");

    for (int c = 0; c < NCHUNK; c++) {
        asm volatile("cp.async.wait_group 0;" ::: "memory");
        __syncthreads();
        if (c + 1 < NCHUNK) {
            cp_stage((c + 1) & 1, c + 1);
            cp_w((c + 1) & 1, c + 1);
            asm volatile("cp.async.commit_group;" ::: "memory");
        }
        convert(c & 1);
        __syncthreads();

        const char* at = smem + OFF_AT;
        const char* wt = smem + OFF_WT + (c & 1) * WT_BUF;
#pragma unroll
        for (int ks = 0; ks < 4; ks++) {
            uint2 a02[2][2], a13[2][2];         // [split][mtile]
#pragma unroll
            for (int sp = 0; sp < 2; sp++)
#pragma unroll
                for (int mt = 0; mt < 2; mt++) {
                    const char* ab = at + sp * SP_BYTES + ks * 4096;
                    int rb = m0 + mt * 16;
                    a02[sp][mt] = *(const uint2*)(ab + (rb + g) * 32 + qc * 8);
                    a13[sp][mt] = *(const uint2*)(ab + (rb + g + 8) * 32 + qc * 8);
                }
#pragma unroll
            for (int nt = 0; nt < 8; nt++) {
                const char* wb = wt + ks * 4096 + (n0 + nt * 8 + g) * 32 + qc * 8;
                uint2 b0 = *(const uint2*)(wb);
                uint2 b1 = *(const uint2*)(wb + SP_BYTES);
#pragma unroll
                for (int mt = 0; mt < 2; mt++) {
                    mma_bf16(acc[mt][nt], a02[0][mt], a13[0][mt], b0);   // a0*w0
                    mma_bf16(acc[mt][nt], a02[0][mt], a13[0][mt], b1);   // a0*w1
                    mma_bf16(acc[mt][nt], a02[1][mt], a13[1][mt], b0);   // a1*w0
                }
            }
        }
        __syncthreads();
    }

    // ---- spill C [128][132] to smem (overwrites dead fp32 stage) ----
    float* Cs = (float*)smem;
#pragma unroll
    for (int mt = 0; mt < 2; mt++)
#pragma unroll
        for (int nt = 0; nt < 8; nt++) {
            int rr = m0 + mt * 16 + g, cc = n0 + nt * 8 + 2 * qc;
            *(float2*)(Cs + rr * CS_STRIDE + cc)       = make_float2(acc[mt][nt].x, acc[mt][nt].y);
            *(float2*)(Cs + (rr + 8) * CS_STRIDE + cc) = make_float2(acc[mt][nt].z, acc[mt][nt].w);
        }
    __syncthreads();

    // ---- epilogue: warp -> tokens warp*16 .. +15 ----
    const bool want_idx = (out_size >= 2 * T_TOKENS * TOPK);
    for (int tt = 0; tt < 16; tt++) {
        int t = warp * 16 + tt, gt = t0 + t;
        bool flag = epilogue_token(Cs + t * CS_STRIDE, gt, lane, noise, mask, out, want_idx);
        if (lane == 0 && flag) {
            int fi = atomicAdd(&g_flag_count, 1);
            if (fi < T_TOKENS) g_flag_list[fi] = gt;
        }
    }
}

// ---- repair: warp = token, lane = 4 consecutive columns.
// Each column chain is EXACT sequential fp32, k ascending (R1/R11-identical).
__global__ void __launch_bounds__(256, 4)
repair_kernel(const float* __restrict__ A, const float* __restrict__ W,
              const float* __restrict__ noise, const int* __restrict__ mask,
              float* __restrict__ out, int out_size)
{
    __shared__ float crow_s[8][NCOL];
    const int warp = threadIdx.x >> 5, lane = threadIdx.x & 31;
    int n = g_flag_count; if (n > T_TOKENS) n = T_TOKENS;
    const bool want_idx = (out_size >= 2 * T_TOKENS * TOPK);

    for (int base = blockIdx.x * 8; base < n; base += gridDim.x * 8) {
        int i = base + warp;
        if (i < n) {
            int gt = g_flag_list[i];
            const float* arow = A + (size_t)gt * D_MODEL;
            float a0 = 0.f, a1 = 0.f, a2 = 0.f, a3 = 0.f;
#pragma unroll 8
            for (int k = 0; k < D_MODEL; k++) {
                float a = arow[k];                              // warp broadcast
                float4 w = *(const float4*)(W + k * NCOL + lane * 4);
                a0 = fmaf(a, w.x, a0); a1 = fmaf(a, w.y, a1);   // 4 independent
                a2 = fmaf(a, w.z, a2); a3 = fmaf(a, w.w, a3);   // sequential chains
            }
            float* cw = crow_s[warp];
            cw[lane * 4 + 0] = a0; cw[lane * 4 + 1] = a1;
            cw[lane * 4 + 2] = a2; cw[lane * 4 + 3] = a3;
            __syncwarp();
            epilogue_token(cw, gt, lane, noise, mask, out, want_idx);
        }
    }
}

extern "C" void kernel_launch(void* const* d_in, const int* in_sizes, int n_in,
                              void* d_out, int out_size)
{
    const float* A     = (const float*)d_in[0];
    const float* W     = (const float*)d_in[1];
    const float* noise = (const float*)d_in[2];
    const int*   mask  = (const int*)d_in[3];
    float* out = (float*)d_out;

    cudaFuncSetAttribute(router_mma_kernel,
                         cudaFuncAttributeMaxDynamicSharedMemorySize, SMEM_SZ);
    zero_kernel<<<1, 32>>>();
    wsplit_kernel<<<512, 256>>>(W);
    router_mma_kernel<<<T_TOKENS / TILE_M, THREADS, SMEM_SZ>>>(A, noise, mask, out, out_size);
    repair_kernel<<<512, 256>>>(A, W, noise, mask, out, out_size);
}

// round 15
// speedup vs baseline: 1.7721x; 1.0009x over previous
#include <cuda_runtime.h>
#include <cuda_bf16.h>
#include <math.h>
#include <stdint.h>

#define T_TOKENS 32768
#define D_MODEL  1024
#define NCOL     128
#define TOPK     8
#define TILE_M   128
#define KC       64
#define NCHUNK   (D_MODEL / KC)
#define THREADS  256

// ---- smem plan (bytes) ----
#define ST_STRIDE 72
#define ST_BYTES  (128 * ST_STRIDE * 4)     // 36864 per buffer
#define OFF_AT    (2 * ST_BYTES)            // 73728 ; A bf16 tiles, 2 splits
#define SP_BYTES  16384                     // one split tile: [4 ks][128 rows][32B]
#define OFF_WT    (OFF_AT + 2 * SP_BYTES)   // 106496 ; W tiles, 2 buf x 2 splits
#define WT_BUF    (2 * SP_BYTES)
#define SMEM_SZ   (OFF_WT + 2 * WT_BUF)     // 172032
#define CS_STRIDE 132

// 5x margin over the ~1e-5*ptop prob-gap error bound of the 2-split GEMM.
// Safe ONLY with the sequential-k repair chain (R2/R12 lesson: repair order
// must stay R1-identical forever).
#define FLAG_TH   5e-5f

__device__ __nv_bfloat16 g_Wsp[2][NCHUNK][8192];  // [split][chunk][ks*2048 + e*16 + pos]
__device__ int g_flag_count;
__device__ int g_flag_list[T_TOKENS];

// ---------------- helpers ----------------
__device__ __forceinline__ void cpa16(unsigned int dst, const void* src) {
    asm volatile("cp.async.cg.shared.global [%0], [%1], 16;" :: "r"(dst), "l"(src));
}
__device__ __forceinline__ int kpos(int k) {        // k in [0,16) -> storage slot
    return (k & 1) + 4 * ((k & 7) >> 1) + 2 * (k >> 3);
}
__device__ __forceinline__ uint32_t cvt2(float xlo, float xhi) {  // lo half = xlo
    uint32_t r;
    asm("cvt.rn.bf16x2.f32 %0, %1, %2;" : "=r"(r) : "f"(xhi), "f"(xlo));
    return r;
}
__device__ __forceinline__ void mma_bf16(float4& c, uint2 a02, uint2 a13, uint2 b) {
    asm("mma.sync.aligned.m16n8k16.row.col.f32.bf16.bf16.f32 "
        "{%0,%1,%2,%3}, {%4,%5,%6,%7}, {%8,%9}, {%0,%1,%2,%3};"
        : "+f"(c.x), "+f"(c.y), "+f"(c.z), "+f"(c.w)
        : "r"(a02.x), "r"(a13.x), "r"(a02.y), "r"(a13.y), "r"(b.x), "r"(b.y));
}

// ---- shared epilogue (identical math in main & repair paths) ----
__device__ __forceinline__ bool epilogue_token(const float* crow, int gt, int lane,
                                               const float* __restrict__ noise,
                                               const int* __restrict__ mask,
                                               float* __restrict__ out, bool want_idx) {
    float lg0 = crow[lane],      lg1 = crow[lane + 32];
    float rn0 = crow[64 + lane], rn1 = crow[96 + lane];
    float ns0 = 1.f / (1.f + expf(-rn0)) + 0.01f;
    float ns1 = 1.f / (1.f + expf(-rn1)) + 0.01f;
    float v0 = fmaf(noise[gt * 64 + lane],      ns0, lg0);
    float v1 = fmaf(noise[gt * 64 + lane + 32], ns1, lg1);

    float mx = fmaxf(v0, v1);
#pragma unroll
    for (int o = 16; o; o >>= 1) mx = fmaxf(mx, __shfl_xor_sync(0xffffffffu, mx, o));
    float p0 = expf(v0 - mx), p1 = expf(v1 - mx);
    float ssum = p0 + p1;
#pragma unroll
    for (int o = 16; o; o >>= 1) ssum += __shfl_xor_sync(0xffffffffu, ssum, o);
    float inv = 1.f / ssum;
    p0 *= inv; p1 *= inv;
    if (mask[gt * 64 + lane] == 0)      p0 = 0.f;
    if (mask[gt * 64 + lane + 32] == 0) p1 = 0.f;

    float sel_p = 0.f; int sel_i = 0; float topsum = 0.f;
    float prev = 0.f, ptop = 0.f; bool flag = false;
#pragma unroll
    for (int it = 0; it < 9; it++) {     // top-9: rank 9 only feeds the gap flag
        float cp; int ci;
        if (p1 > p0) { cp = p1; ci = lane + 32; } else { cp = p0; ci = lane; }
#pragma unroll
        for (int o = 16; o; o >>= 1) {
            float op = __shfl_xor_sync(0xffffffffu, cp, o);
            int   oi = __shfl_xor_sync(0xffffffffu, ci, o);
            if (op > cp || (op == cp && oi < ci)) { cp = op; ci = oi; }
        }
        if (it == 0) ptop = cp;
        else if (prev - cp < FLAG_TH * ptop) flag = true;
        prev = cp;
        if (it < TOPK) {
            topsum += cp;
            if (lane == it) { sel_p = cp; sel_i = ci; }
        }
        if (ci == lane)           p0 = -1.f;
        else if (ci == lane + 32) p1 = -1.f;
    }
    float rinv = 1.f / (topsum + 1e-6f);
    if (lane < TOPK) {
        out[(size_t)gt * TOPK + lane] = sel_p * rinv;
        if (want_idx)
            out[(size_t)T_TOKENS * TOPK + (size_t)gt * TOPK + lane] = (float)sel_i;
    }
    return flag;
}

// ---------------- kernels ----------------
__global__ void zero_kernel() { if (threadIdx.x == 0) g_flag_count = 0; }

__global__ void wsplit_kernel(const float* __restrict__ W) {
    int idx = blockIdx.x * 256 + threadIdx.x;   // 131072 = 1024k x 128e
    int k = idx >> 7, e = idx & 127;
    float x = W[idx];
    __nv_bfloat16 h0 = __float2bfloat16_rn(x);
    float r = x - __bfloat162float(h0);
    __nv_bfloat16 h1 = __float2bfloat16_rn(r);
    int c = k >> 6, ksb = (k >> 4) & 3, kl = k & 15;
    int o = ksb * 2048 + e * 16 + kpos(kl);
    g_Wsp[0][c][o] = h0;
    g_Wsp[1][c][o] = h1;
}

extern __shared__ char smem[];

__global__ void __launch_bounds__(THREADS, 1)
router_mma_kernel(const float* __restrict__ A,
                  const float* __restrict__ noise,
                  const int*   __restrict__ mask,
                  float* __restrict__ out, int out_size)
{
    const int tid = threadIdx.x, warp = tid >> 5, lane = tid & 31;
    const int g = lane >> 2, qc = lane & 3;
    const int t0 = blockIdx.x * TILE_M;
    const int m0 = (warp >> 1) * 32;            // warp token base (local)
    const int n0 = (warp & 1) * 64;             // warp col base
    const uint32_t su = (uint32_t)__cvta_generic_to_shared(smem);

    auto cp_stage = [&](int buf, int c) {       // A fp32: 2048 x 16B
        uint32_t base = su + buf * ST_BYTES;
        const float* asrc = A + (size_t)t0 * D_MODEL + c * KC;
#pragma unroll
        for (int r = 0; r < 8; r++) {
            int q = tid + r * 256, row = q >> 4, ch = q & 15;
            cpa16(base + row * (ST_STRIDE * 4) + ch * 16,
                  asrc + (size_t)row * D_MODEL + ch * 4);
        }
    };
    auto cp_w = [&](int buf, int c) {           // W bf16: 2048 x 16B (pre-permuted)
        uint32_t base = su + OFF_WT + buf * WT_BUF;
#pragma unroll
        for (int r = 0; r < 8; r++) {
            int q = tid + r * 256;
            int sp = q >> 10, o16 = q & 1023;
            cpa16(base + sp * SP_BYTES + o16 * 16, &g_Wsp[sp][c][o16 * 8]);
        }
    };
    auto convert = [&](int buf) {               // fp32 stage -> 2 bf16 split tiles
        const float* st = (const float*)(smem + buf * ST_BYTES);
#pragma unroll
        for (int i = 0; i < 8; i++) {
            int task = warp * 8 + i, rg = task >> 2, blk = task & 3;
            int row = rg * 8 + g;
            const float* sr = st + row * ST_STRIDE + blk * 16;
            float2 xlo = *(const float2*)(sr + 2 * qc);       // k = 2q, 2q+1
            float2 xhi = *(const float2*)(sr + 8 + 2 * qc);   // k = 2q+8, 2q+9
            uint32_t hA = cvt2(xlo.x, xlo.y);
            uint32_t hB = cvt2(xhi.x, xhi.y);
            float rAx = xlo.x - __uint_as_float(hA << 16);
            float rAy = xlo.y - __uint_as_float(hA & 0xFFFF0000u);
            float rBx = xhi.x - __uint_as_float(hB << 16);
            float rBy = xhi.y - __uint_as_float(hB & 0xFFFF0000u);
            uint2 w0 = make_uint2(hA, hB);
            uint2 w1 = make_uint2(cvt2(rAx, rAy), cvt2(rBx, rBy));
            char* dst = smem + OFF_AT + blk * 4096 + row * 32 + qc * 8;
            *(uint2*)(dst)            = w0;
            *(uint2*)(dst + SP_BYTES) = w1;
        }
    };

    float4 acc[2][8];
#pragma unroll
    for (int mt = 0; mt < 2; mt++)
#pragma unroll
        for (int nt = 0; nt < 8; nt++) acc[mt][nt] = make_float4(0.f, 0.f, 0.f, 0.f);

    cp_stage(0, 0); cp_w(0, 0);
    asm volatile("cp.async.commit_group;" ::: "memory");

    for (int c = 0; c < NCHUNK; c++) {
        asm volatile("cp.async.wait_group 0;" ::: "memory");
        __syncthreads();
        if (c + 1 < NCHUNK) {
            cp_stage((c + 1) & 1, c + 1);
            cp_w((c + 1) & 1, c + 1);
            asm volatile("cp.async.commit_group;" ::: "memory");
        }
        convert(c & 1);
        __syncthreads();

        const char* at = smem + OFF_AT;
        const char* wt = smem + OFF_WT + (c & 1) * WT_BUF;
#pragma unroll
        for (int ks = 0; ks < 4; ks++) {
            uint2 a02[2][2], a13[2][2];         // [split][mtile]
#pragma unroll
            for (int sp = 0; sp < 2; sp++)
#pragma unroll
                for (int mt = 0; mt < 2; mt++) {
                    const char* ab = at + sp * SP_BYTES + ks * 4096;
                    int rb = m0 + mt * 16;
                    a02[sp][mt] = *(const uint2*)(ab + (rb + g) * 32 + qc * 8);
                    a13[sp][mt] = *(const uint2*)(ab + (rb + g + 8) * 32 + qc * 8);
                }
#pragma unroll
            for (int nt = 0; nt < 8; nt++) {
                const char* wb = wt + ks * 4096 + (n0 + nt * 8 + g) * 32 + qc * 8;
                uint2 b0 = *(const uint2*)(wb);
                uint2 b1 = *(const uint2*)(wb + SP_BYTES);
#pragma unroll
                for (int mt = 0; mt < 2; mt++) {
                    mma_bf16(acc[mt][nt], a02[0][mt], a13[0][mt], b0);   // a0*w0
                    mma_bf16(acc[mt][nt], a02[0][mt], a13[0][mt], b1);   // a0*w1
                    mma_bf16(acc[mt][nt], a02[1][mt], a13[1][mt], b0);   // a1*w0
                }
            }
        }
        __syncthreads();
    }

    // ---- spill C [128][132] to smem (overwrites dead fp32 stage) ----
    float* Cs = (float*)smem;
#pragma unroll
    for (int mt = 0; mt < 2; mt++)
#pragma unroll
        for (int nt = 0; nt < 8; nt++) {
            int rr = m0 + mt * 16 + g, cc = n0 + nt * 8 + 2 * qc;
            *(float2*)(Cs + rr * CS_STRIDE + cc)       = make_float2(acc[mt][nt].x, acc[mt][nt].y);
            *(float2*)(Cs + (rr + 8) * CS_STRIDE + cc) = make_float2(acc[mt][nt].z, acc[mt][nt].w);
        }
    __syncthreads();

    // ---- epilogue: warp -> tokens warp*16 .. +15 ----
    const bool want_idx = (out_size >= 2 * T_TOKENS * TOPK);
    for (int tt = 0; tt < 16; tt++) {
        int t = warp * 16 + tt, gt = t0 + t;
        bool flag = epilogue_token(Cs + t * CS_STRIDE, gt, lane, noise, mask, out, want_idx);
        if (lane == 0 && flag) {
            int fi = atomicAdd(&g_flag_count, 1);
            if (fi < T_TOKENS) g_flag_list[fi] = gt;
        }
    }
}

// ---- repair: warp = token, lane = 4 consecutive columns.
// Each column chain is EXACT sequential fp32, k ascending (R1/R11/R14-identical).
__global__ void __launch_bounds__(256, 4)
repair_kernel(const float* __restrict__ A, const float* __restrict__ W,
              const float* __restrict__ noise, const int* __restrict__ mask,
              float* __restrict__ out, int out_size)
{
    __shared__ float crow_s[8][NCOL];
    const int warp = threadIdx.x >> 5, lane = threadIdx.x & 31;
    int n = g_flag_count; if (n > T_TOKENS) n = T_TOKENS;
    const bool want_idx = (out_size >= 2 * T_TOKENS * TOPK);

    for (int base = blockIdx.x * 8; base < n; base += gridDim.x * 8) {
        int i = base + warp;
        if (i < n) {
            int gt = g_flag_list[i];
            const float* arow = A + (size_t)gt * D_MODEL;
            float a0 = 0.f, a1 = 0.f, a2 = 0.f, a3 = 0.f;
#pragma unroll 8
            for (int k = 0; k < D_MODEL; k++) {
                float a = arow[k];                              // warp broadcast
                float4 w = *(const float4*)(W + k * NCOL + lane * 4);
                a0 = fmaf(a, w.x, a0); a1 = fmaf(a, w.y, a1);   // 4 independent
                a2 = fmaf(a, w.z, a2); a3 = fmaf(a, w.w, a3);   // sequential chains
            }
            float* cw = crow_s[warp];
            cw[lane * 4 + 0] = a0; cw[lane * 4 + 1] = a1;
            cw[lane * 4 + 2] = a2; cw[lane * 4 + 3] = a3;
            __syncwarp();
            epilogue_token(cw, gt, lane, noise, mask, out, want_idx);
        }
    }
}

extern "C" void kernel_launch(void* const* d_in, const int* in_sizes, int n_in,
                              void* d_out, int out_size)
{
    const float* A     = (const float*)d_in[0];
    const float* W     = (const float*)d_in[1];
    const float* noise = (const float*)d_in[2];
    const int*   mask  = (const int*)d_in[3];
    float* out = (float*)d_out;

    cudaFuncSetAttribute(router_mma_kernel,
                         cudaFuncAttributeMaxDynamicSharedMemorySize, SMEM_SZ);
    zero_kernel<<<1, 32>>>();
    wsplit_kernel<<<512, 256>>>(W);
    router_mma_kernel<<<T_TOKENS / TILE_M, THREADS, SMEM_SZ>>>(A, noise, mask, out, out_size);
    repair_kernel<<<512, 256>>>(A, W, noise, mask, out, out_size);
}

// round 16
// speedup vs baseline: 2.1467x; 1.2114x over previous
#include <cuda_runtime.h>
#include <cuda_bf16.h>
#include <math.h>
#include <stdint.h>

#define T_TOKENS 32768
#define D_MODEL  1024
#define NCOL     128
#define TOPK     8
#define TILE_M   128
#define KC       64
#define NCHUNK   (D_MODEL / KC)
#define THREADS  256

// ---- main-kernel smem plan (bytes) ----
#define ST_STRIDE 72
#define ST_BYTES  (128 * ST_STRIDE * 4)     // 36864 per buffer
#define OFF_AT    (2 * ST_BYTES)            // 73728 ; A bf16 tiles, 2 splits
#define SP_BYTES  16384                     // one split tile: [4 ks][128 rows][32B]
#define OFF_WT    (OFF_AT + 2 * SP_BYTES)   // 106496 ; W tiles, 2 buf x 2 splits
#define WT_BUF    (2 * SP_BYTES)
#define SMEM_SZ   (OFF_WT + 2 * WT_BUF)     // 172032
#define CS_STRIDE 132

// ---- repair-kernel smem plan (bytes) ----
#define RW_TOK    8
#define RW_W      0                          // 2 x [64 k][128 col] f32 = 2 x 32768
#define RW_A      65536                      // 2 x [8 tok][64 k] f32  = 2 x 2048
#define RW_C      69632                      // [8 tok][128] f32 crow  = 4096
#define RW_T      73728                      // token ids [8]
#define RSMEM_SZ  73792

// 5x margin over the ~1e-5*ptop prob-gap error bound of the 2-split GEMM.
// Safe ONLY with the sequential-k repair chain (R2/R12 lesson: repair
// accumulation order must stay R1-identical forever).
#define FLAG_TH   5e-5f

__device__ __nv_bfloat16 g_Wsp[2][NCHUNK][8192];  // [split][chunk][ks*2048 + e*16 + pos]
__device__ int g_flag_count;
__device__ int g_flag_list[T_TOKENS];

// ---------------- helpers ----------------
__device__ __forceinline__ void cpa16(unsigned int dst, const void* src) {
    asm volatile("cp.async.cg.shared.global [%0], [%1], 16;" :: "r"(dst), "l"(src));
}
__device__ __forceinline__ int kpos(int k) {        // k in [0,16) -> storage slot
    return (k & 1) + 4 * ((k & 7) >> 1) + 2 * (k >> 3);
}
__device__ __forceinline__ uint32_t cvt2(float xlo, float xhi) {  // lo half = xlo
    uint32_t r;
    asm("cvt.rn.bf16x2.f32 %0, %1, %2;" : "=r"(r) : "f"(xhi), "f"(xlo));
    return r;
}
__device__ __forceinline__ void mma_bf16(float4& c, uint2 a02, uint2 a13, uint2 b) {
    asm("mma.sync.aligned.m16n8k16.row.col.f32.bf16.bf16.f32 "
        "{%0,%1,%2,%3}, {%4,%5,%6,%7}, {%8,%9}, {%0,%1,%2,%3};"
        : "+f"(c.x), "+f"(c.y), "+f"(c.z), "+f"(c.w)
        : "r"(a02.x), "r"(a13.x), "r"(a02.y), "r"(a13.y), "r"(b.x), "r"(b.y));
}

// ---- shared epilogue (identical math in main & repair paths) ----
__device__ __forceinline__ bool epilogue_token(const float* crow, int gt, int lane,
                                               const float* __restrict__ noise,
                                               const int* __restrict__ mask,
                                               float* __restrict__ out, bool want_idx) {
    float lg0 = crow[lane],      lg1 = crow[lane + 32];
    float rn0 = crow[64 + lane], rn1 = crow[96 + lane];
    float ns0 = 1.f / (1.f + expf(-rn0)) + 0.01f;
    float ns1 = 1.f / (1.f + expf(-rn1)) + 0.01f;
    float v0 = fmaf(noise[gt * 64 + lane],      ns0, lg0);
    float v1 = fmaf(noise[gt * 64 + lane + 32], ns1, lg1);

    float mx = fmaxf(v0, v1);
#pragma unroll
    for (int o = 16; o; o >>= 1) mx = fmaxf(mx, __shfl_xor_sync(0xffffffffu, mx, o));
    float p0 = expf(v0 - mx), p1 = expf(v1 - mx);
    float ssum = p0 + p1;
#pragma unroll
    for (int o = 16; o; o >>= 1) ssum += __shfl_xor_sync(0xffffffffu, ssum, o);
    float inv = 1.f / ssum;
    p0 *= inv; p1 *= inv;
    if (mask[gt * 64 + lane] == 0)      p0 = 0.f;
    if (mask[gt * 64 + lane + 32] == 0) p1 = 0.f;

    float sel_p = 0.f; int sel_i = 0; float topsum = 0.f;
    float prev = 0.f, ptop = 0.f; bool flag = false;
#pragma unroll
    for (int it = 0; it < 9; it++) {     // top-9: rank 9 only feeds the gap flag
        float cp; int ci;
        if (p1 > p0) { cp = p1; ci = lane + 32; } else { cp = p0; ci = lane; }
#pragma unroll
        for (int o = 16; o; o >>= 1) {
            float op = __shfl_xor_sync(0xffffffffu, cp, o);
            int   oi = __shfl_xor_sync(0xffffffffu, ci, o);
            if (op > cp || (op == cp && oi < ci)) { cp = op; ci = oi; }
        }
        if (it == 0) ptop = cp;
        else if (prev - cp < FLAG_TH * ptop) flag = true;
        prev = cp;
        if (it < TOPK) {
            topsum += cp;
            if (lane == it) { sel_p = cp; sel_i = ci; }
        }
        if (ci == lane)           p0 = -1.f;
        else if (ci == lane + 32) p1 = -1.f;
    }
    float rinv = 1.f / (topsum + 1e-6f);
    if (lane < TOPK) {
        out[(size_t)gt * TOPK + lane] = sel_p * rinv;
        if (want_idx)
            out[(size_t)T_TOKENS * TOPK + (size_t)gt * TOPK + lane] = (float)sel_i;
    }
    return flag;
}

// ---------------- kernels ----------------
__global__ void zero_kernel() { if (threadIdx.x == 0) g_flag_count = 0; }

__global__ void wsplit_kernel(const float* __restrict__ W) {
    int idx = blockIdx.x * 256 + threadIdx.x;   // 131072 = 1024k x 128e
    int k = idx >> 7, e = idx & 127;
    float x = W[idx];
    __nv_bfloat16 h0 = __float2bfloat16_rn(x);
    float r = x - __bfloat162float(h0);
    __nv_bfloat16 h1 = __float2bfloat16_rn(r);
    int c = k >> 6, ksb = (k >> 4) & 3, kl = k & 15;
    int o = ksb * 2048 + e * 16 + kpos(kl);
    g_Wsp[0][c][o] = h0;
    g_Wsp[1][c][o] = h1;
}

extern __shared__ char smem[];

__global__ void __launch_bounds__(THREADS, 1)
router_mma_kernel(const float* __restrict__ A,
                  const float* __restrict__ noise,
                  const int*   __restrict__ mask,
                  float* __restrict__ out, int out_size)
{
    const int tid = threadIdx.x, warp = tid >> 5, lane = tid & 31;
    const int g = lane >> 2, qc = lane & 3;
    const int t0 = blockIdx.x * TILE_M;
    const int m0 = (warp >> 1) * 32;            // warp token base (local)
    const int n0 = (warp & 1) * 64;             // warp col base
    const uint32_t su = (uint32_t)__cvta_generic_to_shared(smem);

    auto cp_stage = [&](int buf, int c) {       // A fp32: 2048 x 16B
        uint32_t base = su + buf * ST_BYTES;
        const float* asrc = A + (size_t)t0 * D_MODEL + c * KC;
#pragma unroll
        for (int r = 0; r < 8; r++) {
            int q = tid + r * 256, row = q >> 4, ch = q & 15;
            cpa16(base + row * (ST_STRIDE * 4) + ch * 16,
                  asrc + (size_t)row * D_MODEL + ch * 4);
        }
    };
    auto cp_w = [&](int buf, int c) {           // W bf16: 2048 x 16B (pre-permuted)
        uint32_t base = su + OFF_WT + buf * WT_BUF;
#pragma unroll
        for (int r = 0; r < 8; r++) {
            int q = tid + r * 256;
            int sp = q >> 10, o16 = q & 1023;
            cpa16(base + sp * SP_BYTES + o16 * 16, &g_Wsp[sp][c][o16 * 8]);
        }
    };
    auto convert = [&](int buf) {               // fp32 stage -> 2 bf16 split tiles
        const float* st = (const float*)(smem + buf * ST_BYTES);
#pragma unroll
        for (int i = 0; i < 8; i++) {
            int task = warp * 8 + i, rg = task >> 2, blk = task & 3;
            int row = rg * 8 + g;
            const float* sr = st + row * ST_STRIDE + blk * 16;
            float2 xlo = *(const float2*)(sr + 2 * qc);       // k = 2q, 2q+1
            float2 xhi = *(const float2*)(sr + 8 + 2 * qc);   // k = 2q+8, 2q+9
            uint32_t hA = cvt2(xlo.x, xlo.y);
            uint32_t hB = cvt2(xhi.x, xhi.y);
            float rAx = xlo.x - __uint_as_float(hA << 16);
            float rAy = xlo.y - __uint_as_float(hA & 0xFFFF0000u);
            float rBx = xhi.x - __uint_as_float(hB << 16);
            float rBy = xhi.y - __uint_as_float(hB & 0xFFFF0000u);
            uint2 w0 = make_uint2(hA, hB);
            uint2 w1 = make_uint2(cvt2(rAx, rAy), cvt2(rBx, rBy));
            char* dst = smem + OFF_AT + blk * 4096 + row * 32 + qc * 8;
            *(uint2*)(dst)            = w0;
            *(uint2*)(dst + SP_BYTES) = w1;
        }
    };

    float4 acc[2][8];
#pragma unroll
    for (int mt = 0; mt < 2; mt++)
#pragma unroll
        for (int nt = 0; nt < 8; nt++) acc[mt][nt] = make_float4(0.f, 0.f, 0.f, 0.f);

    cp_stage(0, 0); cp_w(0, 0);
    asm volatile("cp.async.commit_group;" ::: "memory");

    for (int c = 0; c < NCHUNK; c++) {
        asm volatile("cp.async.wait_group 0;" ::: "memory");
        __syncthreads();
        if (c + 1 < NCHUNK) {
            cp_stage((c + 1) & 1, c + 1);
            cp_w((c + 1) & 1, c + 1);
            asm volatile("cp.async.commit_group;" ::: "memory");
        }
        convert(c & 1);
        __syncthreads();

        const char* at = smem + OFF_AT;
        const char* wt = smem + OFF_WT + (c & 1) * WT_BUF;
#pragma unroll
        for (int ks = 0; ks < 4; ks++) {
            uint2 a02[2][2], a13[2][2];         // [split][mtile]
#pragma unroll
            for (int sp = 0; sp < 2; sp++)
#pragma unroll
                for (int mt = 0; mt < 2; mt++) {
                    const char* ab = at + sp * SP_BYTES + ks * 4096;
                    int rb = m0 + mt * 16;
                    a02[sp][mt] = *(const uint2*)(ab + (rb + g) * 32 + qc * 8);
                    a13[sp][mt] = *(const uint2*)(ab + (rb + g + 8) * 32 + qc * 8);
                }
#pragma unroll
            for (int nt = 0; nt < 8; nt++) {
                const char* wb = wt + ks * 4096 + (n0 + nt * 8 + g) * 32 + qc * 8;
                uint2 b0 = *(const uint2*)(wb);
                uint2 b1 = *(const uint2*)(wb + SP_BYTES);
#pragma unroll
                for (int mt = 0; mt < 2; mt++) {
                    mma_bf16(acc[mt][nt], a02[0][mt], a13[0][mt], b0);   // a0*w0
                    mma_bf16(acc[mt][nt], a02[0][mt], a13[0][mt], b1);   // a0*w1
                    mma_bf16(acc[mt][nt], a02[1][mt], a13[1][mt], b0);   // a1*w0
                }
            }
        }
        __syncthreads();
    }

    // ---- spill C [128][132] to smem (overwrites dead fp32 stage) ----
    float* Cs = (float*)smem;
#pragma unroll
    for (int mt = 0; mt < 2; mt++)
#pragma unroll
        for (int nt = 0; nt < 8; nt++) {
            int rr = m0 + mt * 16 + g, cc = n0 + nt * 8 + 2 * qc;
            *(float2*)(Cs + rr * CS_STRIDE + cc)       = make_float2(acc[mt][nt].x, acc[mt][nt].y);
            *(float2*)(Cs + (rr + 8) * CS_STRIDE + cc) = make_float2(acc[mt][nt].z, acc[mt][nt].w);
        }
    __syncthreads();

    // ---- epilogue: warp -> tokens warp*16 .. +15 ----
    const bool want_idx = (out_size >= 2 * T_TOKENS * TOPK);
    for (int tt = 0; tt < 16; tt++) {
        int t = warp * 16 + tt, gt = t0 + t;
        bool flag = epilogue_token(Cs + t * CS_STRIDE, gt, lane, noise, mask, out, want_idx);
        if (lane == 0 && flag) {
            int fi = atomicAdd(&g_flag_count, 1);
            if (fi < T_TOKENS) g_flag_list[fi] = gt;
        }
    }
}

// ---- repair: block = 8 tokens, warp = token, lane = 4 consecutive columns.
// W + A staged through smem (cp.async double-buffered); the per-column chain
// is the EXACT sequential fp32 fmaf chain, k ascending (R1/R14/R15-identical).
__global__ void __launch_bounds__(256, 2)
repair_kernel(const float* __restrict__ A, const float* __restrict__ W,
              const float* __restrict__ noise, const int* __restrict__ mask,
              float* __restrict__ out, int out_size)
{
    const int tid = threadIdx.x, warp = tid >> 5, lane = tid & 31;
    const uint32_t su = (uint32_t)__cvta_generic_to_shared(smem);
    int* stok = (int*)(smem + RW_T);
    int n = g_flag_count; if (n > T_TOKENS) n = T_TOKENS;
    const bool want_idx = (out_size >= 2 * T_TOKENS * TOPK);

    auto cp_chunk = [&](int buf, int c) {
        // W chunk: 32 KB contiguous (64 k rows x 128 cols f32)
        const float* wsrc = W + c * KC * NCOL;
#pragma unroll
        for (int r = 0; r < 8; r++) {
            int q = tid + r * 256;
            cpa16(su + RW_W + buf * 32768 + q * 16, wsrc + q * 4);
        }
        // A slices: 8 tokens x 256 B (threads 0..127)
        if (tid < 128) {
            int t = tid >> 4, ch = tid & 15;
            int gt = stok[t];
            if (gt >= 0)
                cpa16(su + RW_A + buf * 2048 + t * 256 + ch * 16,
                      A + (size_t)gt * D_MODEL + c * KC + ch * 4);
        }
        asm volatile("cp.async.commit_group;" ::: "memory");
    };

    for (int base = blockIdx.x * RW_TOK; base < n; base += gridDim.x * RW_TOK) {
        if (tid < RW_TOK)
            stok[tid] = (base + tid < n) ? g_flag_list[base + tid] : -1;
        __syncthreads();

        cp_chunk(0, 0);
        float a0 = 0.f, a1 = 0.f, a2 = 0.f, a3 = 0.f;
        const bool active = (stok[warp] >= 0);

        for (int c = 0; c < NCHUNK; c++) {
            asm volatile("cp.async.wait_group 0;" ::: "memory");
            __syncthreads();
            if (c + 1 < NCHUNK) cp_chunk((c + 1) & 1, c + 1);

            if (active) {
                const float* sw = (const float*)(smem + RW_W + (c & 1) * 32768);
                const float* sa = (const float*)(smem + RW_A + (c & 1) * 2048) + warp * KC;
#pragma unroll 8
                for (int kk = 0; kk < KC; kk++) {
                    float a = sa[kk];                               // broadcast LDS
                    float4 w = *(const float4*)(sw + kk * NCOL + lane * 4);
                    a0 = fmaf(a, w.x, a0); a1 = fmaf(a, w.y, a1);   // 4 independent
                    a2 = fmaf(a, w.z, a2); a3 = fmaf(a, w.w, a3);   // sequential chains
                }
            }
            __syncthreads();
        }

        if (active) {
            float* cw = (float*)(smem + RW_C) + warp * NCOL;
            cw[lane * 4 + 0] = a0; cw[lane * 4 + 1] = a1;
            cw[lane * 4 + 2] = a2; cw[lane * 4 + 3] = a3;
            __syncwarp();
            epilogue_token(cw, stok[warp], lane, noise, mask, out, want_idx);
        }
        __syncthreads();
    }
}

extern "C" void kernel_launch(void* const* d_in, const int* in_sizes, int n_in,
                              void* d_out, int out_size)
{
    const float* A     = (const float*)d_in[0];
    const float* W     = (const float*)d_in[1];
    const float* noise = (const float*)d_in[2];
    const int*   mask  = (const int*)d_in[3];
    float* out = (float*)d_out;

    cudaFuncSetAttribute(router_mma_kernel,
                         cudaFuncAttributeMaxDynamicSharedMemorySize, SMEM_SZ);
    cudaFuncSetAttribute(repair_kernel,
                         cudaFuncAttributeMaxDynamicSharedMemorySize, RSMEM_SZ);
    zero_kernel<<<1, 32>>>();
    wsplit_kernel<<<512, 256>>>(W);
    router_mma_kernel<<<T_TOKENS / TILE_M, THREADS, SMEM_SZ>>>(A, noise, mask, out, out_size);
    repair_kernel<<<256, 256, RSMEM_SZ>>>(A, W, noise, mask, out, out_size);
}

// round 17
// speedup vs baseline: 2.5742x; 1.1991x over previous
#include <cuda_runtime.h>
#include <cuda_bf16.h>
#include <math.h>
#include <stdint.h>

#define T_TOKENS 32768
#define D_MODEL  1024
#define NCOL     128
#define TOPK     8
#define TILE_M   128
#define KC       32
#define NCHUNK   (D_MODEL / KC)      // 32
#define THREADS  256

// ---- main-kernel smem plan (bytes) ----
#define ST_STRIDE 36
#define ST_BYTES  (128 * ST_STRIDE * 4)     // 18432 per buffer
#define OFF_AT    (2 * ST_BYTES)            // 36864 ; A bf16 tiles, 2 splits
#define SP_BYTES  8192                      // one split tile: [2 ks][128 rows][32B]
#define OFF_WT    (OFF_AT + 2 * SP_BYTES)   // 53248 ; W tiles, 2 buf x 2 splits
#define WT_BUF    (2 * SP_BYTES)            // 16384
#define SMEM_SZ   (OFF_WT + 2 * WT_BUF)     // 86016  (Cs 128x132x4=67584 fits)
#define CS_STRIDE 132

// ---- repair-kernel smem plan (bytes) ----
#define KCR       64
#define NCHUNK_R  (D_MODEL / KCR)           // 16
#define RW_TOK    8
#define RW_W      0                          // 4 x [64 k][128 col] f32 = 4 x 32768
#define RW_A      131072                     // 4 x [8 tok][64 k] f32  = 4 x 2048
#define RW_C      139264                     // [8 tok][128] f32 crow  = 4096
#define RW_T      143360                     // token ids [8]
#define RSMEM_SZ  143424

// 5x margin over the ~1e-5*ptop prob-gap error bound of the 2-split GEMM.
// Safe ONLY with the sequential-k repair chain (R2/R12 lesson: repair
// accumulation order must stay R1-identical forever).
#define FLAG_TH   5e-5f

__device__ __nv_bfloat16 g_Wsp[2][NCHUNK][4096];  // [split][chunk][ks*2048 + e*16 + pos]
__device__ int g_flag_count;
__device__ int g_flag_list[T_TOKENS];

// ---------------- helpers ----------------
__device__ __forceinline__ void cpa16(unsigned int dst, const void* src) {
    asm volatile("cp.async.cg.shared.global [%0], [%1], 16;" :: "r"(dst), "l"(src));
}
__device__ __forceinline__ int kpos(int k) {        // k in [0,16) -> storage slot
    return (k & 1) + 4 * ((k & 7) >> 1) + 2 * (k >> 3);
}
__device__ __forceinline__ uint32_t cvt2(float xlo, float xhi) {  // lo half = xlo
    uint32_t r;
    asm("cvt.rn.bf16x2.f32 %0, %1, %2;" : "=r"(r) : "f"(xhi), "f"(xlo));
    return r;
}
__device__ __forceinline__ void mma_bf16(float4& c, uint2 a02, uint2 a13, uint2 b) {
    asm("mma.sync.aligned.m16n8k16.row.col.f32.bf16.bf16.f32 "
        "{%0,%1,%2,%3}, {%4,%5,%6,%7}, {%8,%9}, {%0,%1,%2,%3};"
        : "+f"(c.x), "+f"(c.y), "+f"(c.z), "+f"(c.w)
        : "r"(a02.x), "r"(a13.x), "r"(a02.y), "r"(a13.y), "r"(b.x), "r"(b.y));
}

// ---- shared epilogue (identical math in main & repair paths) ----
__device__ __forceinline__ bool epilogue_token(const float* crow, int gt, int lane,
                                               const float* __restrict__ noise,
                                               const int* __restrict__ mask,
                                               float* __restrict__ out, bool want_idx) {
    float lg0 = crow[lane],      lg1 = crow[lane + 32];
    float rn0 = crow[64 + lane], rn1 = crow[96 + lane];
    float ns0 = 1.f / (1.f + expf(-rn0)) + 0.01f;
    float ns1 = 1.f / (1.f + expf(-rn1)) + 0.01f;
    float v0 = fmaf(noise[gt * 64 + lane],      ns0, lg0);
    float v1 = fmaf(noise[gt * 64 + lane + 32], ns1, lg1);

    float mx = fmaxf(v0, v1);
#pragma unroll
    for (int o = 16; o; o >>= 1) mx = fmaxf(mx, __shfl_xor_sync(0xffffffffu, mx, o));
    float p0 = expf(v0 - mx), p1 = expf(v1 - mx);
    float ssum = p0 + p1;
#pragma unroll
    for (int o = 16; o; o >>= 1) ssum += __shfl_xor_sync(0xffffffffu, ssum, o);
    float inv = 1.f / ssum;
    p0 *= inv; p1 *= inv;
    if (mask[gt * 64 + lane] == 0)      p0 = 0.f;
    if (mask[gt * 64 + lane + 32] == 0) p1 = 0.f;

    float sel_p = 0.f; int sel_i = 0; float topsum = 0.f;
    float prev = 0.f, ptop = 0.f; bool flag = false;
#pragma unroll
    for (int it = 0; it < 9; it++) {     // top-9: rank 9 only feeds the gap flag
        float cp; int ci;
        if (p1 > p0) { cp = p1; ci = lane + 32; } else { cp = p0; ci = lane; }
#pragma unroll
        for (int o = 16; o; o >>= 1) {
            float op = __shfl_xor_sync(0xffffffffu, cp, o);
            int   oi = __shfl_xor_sync(0xffffffffu, ci, o);
            if (op > cp || (op == cp && oi < ci)) { cp = op; ci = oi; }
        }
        if (it == 0) ptop = cp;
        else if (prev - cp < FLAG_TH * ptop) flag = true;
        prev = cp;
        if (it < TOPK) {
            topsum += cp;
            if (lane == it) { sel_p = cp; sel_i = ci; }
        }
        if (ci == lane)           p0 = -1.f;
        else if (ci == lane + 32) p1 = -1.f;
    }
    float rinv = 1.f / (topsum + 1e-6f);
    if (lane < TOPK) {
        out[(size_t)gt * TOPK + lane] = sel_p * rinv;
        if (want_idx)
            out[(size_t)T_TOKENS * TOPK + (size_t)gt * TOPK + lane] = (float)sel_i;
    }
    return flag;
}

// ---------------- kernels ----------------
__global__ void zero_kernel() { if (threadIdx.x == 0) g_flag_count = 0; }

__global__ void wsplit_kernel(const float* __restrict__ W) {
    int idx = blockIdx.x * 256 + threadIdx.x;   // 131072 = 1024k x 128e
    int k = idx >> 7, e = idx & 127;
    float x = W[idx];
    __nv_bfloat16 h0 = __float2bfloat16_rn(x);
    float r = x - __bfloat162float(h0);
    __nv_bfloat16 h1 = __float2bfloat16_rn(r);
    int c = k >> 5, ksb = (k >> 4) & 1, kl = k & 15;
    int o = ksb * 2048 + e * 16 + kpos(kl);
    g_Wsp[0][c][o] = h0;
    g_Wsp[1][c][o] = h1;
}

extern __shared__ char smem[];

__global__ void __launch_bounds__(THREADS, 2)
router_mma_kernel(const float* __restrict__ A,
                  const float* __restrict__ noise,
                  const int*   __restrict__ mask,
                  float* __restrict__ out, int out_size)
{
    const int tid = threadIdx.x, warp = tid >> 5, lane = tid & 31;
    const int g = lane >> 2, qc = lane & 3;
    const int t0 = blockIdx.x * TILE_M;
    const int m0 = (warp >> 1) * 32;            // warp token base (local)
    const int n0 = (warp & 1) * 64;             // warp col base
    const uint32_t su = (uint32_t)__cvta_generic_to_shared(smem);

    auto cp_stage = [&](int buf, int c) {       // A fp32 chunk: 1024 x 16B, 4/thread
        uint32_t base = su + buf * ST_BYTES;
        const float* asrc = A + (size_t)t0 * D_MODEL + c * KC;
#pragma unroll
        for (int r = 0; r < 4; r++) {
            int q = tid + r * 256, row = q >> 3, ch = q & 7;
            cpa16(base + row * (ST_STRIDE * 4) + ch * 16,
                  asrc + (size_t)row * D_MODEL + ch * 4);
        }
    };
    auto cp_w = [&](int buf, int c) {           // W bf16: 1024 x 16B, 4/thread
        uint32_t base = su + OFF_WT + buf * WT_BUF;
#pragma unroll
        for (int r = 0; r < 4; r++) {
            int q = tid + r * 256;
            int sp = q >> 9, rem = q & 511;
            cpa16(base + sp * SP_BYTES + rem * 16, &g_Wsp[sp][c][rem * 8]);
        }
    };
    auto convert = [&](int buf) {               // fp32 stage -> 2 bf16 split tiles
        const float* st = (const float*)(smem + buf * ST_BYTES);
#pragma unroll
        for (int i = 0; i < 4; i++) {
            int task = warp * 4 + i, rg = task >> 1, blk = task & 1;
            int row = rg * 8 + g;
            const float* sr = st + row * ST_STRIDE + blk * 16;
            float2 xlo = *(const float2*)(sr + 2 * qc);       // k = 2q, 2q+1
            float2 xhi = *(const float2*)(sr + 8 + 2 * qc);   // k = 2q+8, 2q+9
            uint32_t hA = cvt2(xlo.x, xlo.y);
            uint32_t hB = cvt2(xhi.x, xhi.y);
            float rAx = xlo.x - __uint_as_float(hA << 16);
            float rAy = xlo.y - __uint_as_float(hA & 0xFFFF0000u);
            float rBx = xhi.x - __uint_as_float(hB << 16);
            float rBy = xhi.y - __uint_as_float(hB & 0xFFFF0000u);
            uint2 w0 = make_uint2(hA, hB);
            uint2 w1 = make_uint2(cvt2(rAx, rAy), cvt2(rBx, rBy));
            char* dst = smem + OFF_AT + blk * 4096 + row * 32 + qc * 8;
            *(uint2*)(dst)            = w0;
            *(uint2*)(dst + SP_BYTES) = w1;
        }
    };

    float4 acc[2][8];
#pragma unroll
    for (int mt = 0; mt < 2; mt++)
#pragma unroll
        for (int nt = 0; nt < 8; nt++) acc[mt][nt] = make_float4(0.f, 0.f, 0.f, 0.f);

    cp_stage(0, 0); cp_w(0, 0);
    asm volatile("cp.async.commit_group;" ::: "memory");

    for (int c = 0; c < NCHUNK; c++) {
        asm volatile("cp.async.wait_group 0;" ::: "memory");
        __syncthreads();
        if (c + 1 < NCHUNK) {
            cp_stage((c + 1) & 1, c + 1);
            cp_w((c + 1) & 1, c + 1);
            asm volatile("cp.async.commit_group;" ::: "memory");
        }
        convert(c & 1);
        __syncthreads();

        const char* at = smem + OFF_AT;
        const char* wt = smem + OFF_WT + (c & 1) * WT_BUF;
#pragma unroll
        for (int ks = 0; ks < 2; ks++) {        // k order across chunks == R16
            uint2 a02[2][2], a13[2][2];         // [split][mtile]
#pragma unroll
            for (int sp = 0; sp < 2; sp++)
#pragma unroll
                for (int mt = 0; mt < 2; mt++) {
                    const char* ab = at + sp * SP_BYTES + ks * 4096;
                    int rb = m0 + mt * 16;
                    a02[sp][mt] = *(const uint2*)(ab + (rb + g) * 32 + qc * 8);
                    a13[sp][mt] = *(const uint2*)(ab + (rb + g + 8) * 32 + qc * 8);
                }
#pragma unroll
            for (int nt = 0; nt < 8; nt++) {
                const char* wb = wt + ks * 4096 + (n0 + nt * 8 + g) * 32 + qc * 8;
                uint2 b0 = *(const uint2*)(wb);
                uint2 b1 = *(const uint2*)(wb + SP_BYTES);
#pragma unroll
                for (int mt = 0; mt < 2; mt++) {
                    mma_bf16(acc[mt][nt], a02[0][mt], a13[0][mt], b0);   // a0*w0
                    mma_bf16(acc[mt][nt], a02[0][mt], a13[0][mt], b1);   // a0*w1
                    mma_bf16(acc[mt][nt], a02[1][mt], a13[1][mt], b0);   // a1*w0
                }
            }
        }
        __syncthreads();
    }

    // ---- spill C [128][132] to smem ----
    float* Cs = (float*)smem;
#pragma unroll
    for (int mt = 0; mt < 2; mt++)
#pragma unroll
        for (int nt = 0; nt < 8; nt++) {
            int rr = m0 + mt * 16 + g, cc = n0 + nt * 8 + 2 * qc;
            *(float2*)(Cs + rr * CS_STRIDE + cc)       = make_float2(acc[mt][nt].x, acc[mt][nt].y);
            *(float2*)(Cs + (rr + 8) * CS_STRIDE + cc) = make_float2(acc[mt][nt].z, acc[mt][nt].w);
        }
    __syncthreads();

    // ---- epilogue: warp -> tokens warp*16 .. +15 ----
    const bool want_idx = (out_size >= 2 * T_TOKENS * TOPK);
    for (int tt = 0; tt < 16; tt++) {
        int t = warp * 16 + tt, gt = t0 + t;
        bool flag = epilogue_token(Cs + t * CS_STRIDE, gt, lane, noise, mask, out, want_idx);
        if (lane == 0 && flag) {
            int fi = atomicAdd(&g_flag_count, 1);
            if (fi < T_TOKENS) g_flag_list[fi] = gt;
        }
    }
}

// ---- repair: block = 8 tokens, warp = token, lane = 4 consecutive columns.
// 4-stage cp.async pipeline; the per-column chain is the EXACT sequential
// fp32 fmaf chain, k ascending (R1/R14/R15/R16-identical).
__global__ void __launch_bounds__(256, 1)
repair_kernel(const float* __restrict__ A, const float* __restrict__ W,
              const float* __restrict__ noise, const int* __restrict__ mask,
              float* __restrict__ out, int out_size)
{
    const int tid = threadIdx.x, warp = tid >> 5, lane = tid & 31;
    const uint32_t su = (uint32_t)__cvta_generic_to_shared(smem);
    int* stok = (int*)(smem + RW_T);
    int n = g_flag_count; if (n > T_TOKENS) n = T_TOKENS;
    const bool want_idx = (out_size >= 2 * T_TOKENS * TOPK);

    auto cp_chunk = [&](int c) {
        int buf = c & 3;
        const float* wsrc = W + c * KCR * NCOL;     // 32 KB contiguous
#pragma unroll
        for (int r = 0; r < 8; r++) {
            int q = tid + r * 256;
            cpa16(su + RW_W + buf * 32768 + q * 16, wsrc + q * 4);
        }
        if (tid < 128) {                            // A slices: 8 tok x 256 B
            int t = tid >> 4, ch = tid & 15;
            int gt = stok[t];
            if (gt >= 0)
                cpa16(su + RW_A + buf * 2048 + t * 256 + ch * 16,
                      A + (size_t)gt * D_MODEL + c * KCR + ch * 4);
        }
        asm volatile("cp.async.commit_group;" ::: "memory");
    };

    for (int base = blockIdx.x * RW_TOK; base < n; base += gridDim.x * RW_TOK) {
        if (tid < RW_TOK)
            stok[tid] = (base + tid < n) ? g_flag_list[base + tid] : -1;
        __syncthreads();

        cp_chunk(0); cp_chunk(1); cp_chunk(2);      // 3 in flight
        float a0 = 0.f, a1 = 0.f, a2 = 0.f, a3 = 0.f;
        const bool active = (stok[warp] >= 0);

        for (int c = 0; c < NCHUNK_R; c++) {
            if (c + 3 < NCHUNK_R) {
                cp_chunk(c + 3);
                asm volatile("cp.async.wait_group 3;" ::: "memory");   // chunk c done
            } else {
                asm volatile("cp.async.wait_group 0;" ::: "memory");   // tail
            }
            __syncthreads();

            if (active) {
                const float* sw = (const float*)(smem + RW_W + (c & 3) * 32768);
                const float* sa = (const float*)(smem + RW_A + (c & 3) * 2048) + warp * KCR;
#pragma unroll 8
                for (int kk = 0; kk < KCR; kk++) {
                    float a = sa[kk];                               // broadcast LDS
                    float4 w = *(const float4*)(sw + kk * NCOL + lane * 4);
                    a0 = fmaf(a, w.x, a0); a1 = fmaf(a, w.y, a1);   // 4 independent
                    a2 = fmaf(a, w.z, a2); a3 = fmaf(a, w.w, a3);   // sequential chains
                }
            }
            __syncthreads();
        }

        if (active) {
            float* cw = (float*)(smem + RW_C) + warp * NCOL;
            cw[lane * 4 + 0] = a0; cw[lane * 4 + 1] = a1;
            cw[lane * 4 + 2] = a2; cw[lane * 4 + 3] = a3;
            __syncwarp();
            epilogue_token(cw, stok[warp], lane, noise, mask, out, want_idx);
        }
        __syncthreads();
    }
}

extern "C" void kernel_launch(void* const* d_in, const int* in_sizes, int n_in,
                              void* d_out, int out_size)
{
    const float* A     = (const float*)d_in[0];
    const float* W     = (const float*)d_in[1];
    const float* noise = (const float*)d_in[2];
    const int*   mask  = (const int*)d_in[3];
    float* out = (float*)d_out;

    cudaFuncSetAttribute(router_mma_kernel,
                         cudaFuncAttributeMaxDynamicSharedMemorySize, SMEM_SZ);
    cudaFuncSetAttribute(repair_kernel,
                         cudaFuncAttributeMaxDynamicSharedMemorySize, RSMEM_SZ);
    zero_kernel<<<1, 32>>>();
    wsplit_kernel<<<512, 256>>>(W);
    router_mma_kernel<<<T_TOKENS / TILE_M, THREADS, SMEM_SZ>>>(A, noise, mask, out, out_size);
    repair_kernel<<<256, 256, RSMEM_SZ>>>(A, W, noise, mask, out, out_size);
}